// round 13
// baseline (speedup 1.0000x reference)
#include <cuda_runtime.h>
#include <cuda_bf16.h>
#include <cstdint>

#define NN    30000
#define MP    30080          // rows padded to 235*128
#define NE    240000
#define EMB   300
#define EMBP  320            // padded emb
#define HID   600
#define HIDP  640            // padded hidden (stride)
#define HIDE  608            // effective K for GEMM2 (cols 608..639 of t1 are exact zeros)
#define NL    5
#define NB_SCAN 118          // ceil(30000/256)

// ---------------- scratch (device globals: allocation-free, zero-init) ----------------
__device__ float          g_h  [(size_t)NN * EMBP];     // layer-0 features only
__device__ float          g_h2 [(size_t)MP * EMBP];     // raw GEMM2 output (pre-BN)
__device__ __nv_bfloat16  g_ah [(size_t)MP * EMBP];     // pad rows/cols stay 0
__device__ __nv_bfloat16  g_al [(size_t)MP * EMBP];
__device__ __nv_bfloat16  g_t1h[(size_t)MP * HIDP];
__device__ __nv_bfloat16  g_t1l[(size_t)MP * HIDP];
__device__ __nv_bfloat16  g_w1th[(size_t)NL * HIDP * EMBP]; // W1^T split [l][n=640][k=320]
__device__ __nv_bfloat16  g_w1tl[(size_t)NL * HIDP * EMBP];
__device__ __nv_bfloat16  g_w2th[(size_t)NL * EMBP * HIDP]; // W2^T split [l][n=320][k=640]
__device__ __nv_bfloat16  g_w2tl[(size_t)NL * EMBP * HIDP];
__device__ float          g_b1p[NL * HIDP];
__device__ float          g_b2p[NL * EMBP];
__device__ float          g_stats[2 * EMB];
// CSR scratch
__device__ int            g_deg[NN];
__device__ int            g_rowptr[NN + 1];
__device__ int            g_cursor[NN];
__device__ int            g_bsum[NB_SCAN];
__device__ int            g_boff[NB_SCAN];
__device__ int            g_csr[NE];     // packed: src | a0<<16 | a1<<20

// ================= PTX helpers =================
__device__ __forceinline__ uint32_t smem_u32(const void* p) {
    uint32_t a;
    asm("{ .reg .u64 t; cvta.to.shared.u64 t, %1; cvt.u32.u64 %0, t; }" : "=r"(a) : "l"(p));
    return a;
}
__device__ __forceinline__ void cpa16(uint32_t s, const void* g) {
    asm volatile("cp.async.cg.shared.global [%0], [%1], 16;" :: "r"(s), "l"(g) : "memory");
}
#define CP_COMMIT() asm volatile("cp.async.commit_group;" ::: "memory")
#define CP_WAIT(n)  asm volatile("cp.async.wait_group %0;" :: "n"(n) : "memory")

__device__ __forceinline__ void ldm4(uint32_t* r, uint32_t a) {
    asm volatile("ldmatrix.sync.aligned.m8n8.x4.shared.b16 {%0,%1,%2,%3}, [%4];"
                 : "=r"(r[0]), "=r"(r[1]), "=r"(r[2]), "=r"(r[3]) : "r"(a));
}
__device__ __forceinline__ void mma_bf16(float* c, const uint32_t* a, uint32_t b0, uint32_t b1) {
    asm volatile(
        "mma.sync.aligned.m16n8k16.row.col.f32.bf16.bf16.f32 "
        "{%0,%1,%2,%3}, {%4,%5,%6,%7}, {%8,%9}, {%0,%1,%2,%3};"
        : "+f"(c[0]), "+f"(c[1]), "+f"(c[2]), "+f"(c[3])
        : "r"(a[0]), "r"(a[1]), "r"(a[2]), "r"(a[3]), "r"(b0), "r"(b1));
}

// SW64 swizzle for 64-byte rows
__device__ __forceinline__ uint32_t sw64(uint32_t off) {
    return off ^ ((off >> 3) & 0x30);
}

// ================= HMMA GEMM (bf16x3 split) — R7/R11 config, frozen =================
// CTA tile 128x64, 8 warps (4M x 2N), warp tile 32x32.
// K-chunk 32, 4-stage cp.async pipeline (24KB/stage, 96KB total -> 2 CTAs/SM).
// KP = row stride (elements); KEFF = contracted K (KEFF <= KP, multiple of 32).
// EPI==1: relu(acc+bias) -> split bf16 to O1/O2 (row stride NP); block(0,0) zeroes stats
// EPI==2: acc+bias -> f32 O1 (row stride NP), fused BN column sum/sumsq into stats
template <int KP, int KEFF, int NP, int EPI>
__global__ void __launch_bounds__(256, 2)
k_gemm(const __nv_bfloat16* __restrict__ Ah, const __nv_bfloat16* __restrict__ Al,
       const __nv_bfloat16* __restrict__ Bh, const __nv_bfloat16* __restrict__ Bl,
       const float* __restrict__ bias, void* __restrict__ O1, void* __restrict__ O2,
       float* __restrict__ stats)
{
    constexpr int NKC = KEFF / 32;
    constexpr uint32_t STG = 24576;
    constexpr uint32_t A_H = 0, A_L = 8192, B_H = 16384, B_L = 20480;

    __shared__ float sstat[128];        // [0:64) col sums, [64:128) col sumsqs

    extern __shared__ char smem[];
    const uint32_t sb = smem_u32(smem);
    const int tid  = threadIdx.x;
    const int lane = tid & 31;
    const int warp = tid >> 5;
    const int wm   = warp & 3;           // 0..3 (M)
    const int wn   = warp >> 2;          // 0..1 (N)
    const int bm   = blockIdx.y * 128;
    const int bn   = blockIdx.x * 64;

    if (EPI == 1 && blockIdx.x == 0 && blockIdx.y == 0) {
        for (int i = tid; i < 2 * EMB; i += 256) stats[i] = 0.f;
    }
    if (EPI == 2 && tid < 128) sstat[tid] = 0.f;

    const size_t rs = (size_t)KP * 2;    // row stride bytes

    auto load_stage = [&](int buf, int kc) {
        uint32_t s0 = sb + buf * STG;
        int k0 = kc * 32;
        const char* ahp = (const char*)(Ah + (size_t)bm * KP + k0);
        const char* alp = (const char*)(Al + (size_t)bm * KP + k0);
        const char* bhp = (const char*)(Bh + (size_t)bn * KP + k0);
        const char* blp = (const char*)(Bl + (size_t)bn * KP + k0);
        #pragma unroll
        for (int i = 0; i < 2; i++) {       // A: 128 rows x 4 x 16B = 512 chunks/half
            int idx = tid + 256 * i;
            int r = idx >> 2, c = (idx & 3) * 16;
            uint32_t sw = sw64((uint32_t)(r * 64 + c));
            cpa16(s0 + A_H + sw, ahp + (size_t)r * rs + c);
            cpa16(s0 + A_L + sw, alp + (size_t)r * rs + c);
        }
        {                                   // B: 64 rows x 4 x 16B = 256 chunks/half
            int r = tid >> 2, c = (tid & 3) * 16;
            uint32_t sw = sw64((uint32_t)(r * 64 + c));
            cpa16(s0 + B_H + sw, bhp + (size_t)r * rs + c);
            cpa16(s0 + B_L + sw, blp + (size_t)r * rs + c);
        }
    };

    float acc[2][4][4];
    #pragma unroll
    for (int mi = 0; mi < 2; mi++)
        #pragma unroll
        for (int ni = 0; ni < 4; ni++)
            #pragma unroll
            for (int q = 0; q < 4; q++) acc[mi][ni][q] = 0.f;

    load_stage(0, 0); CP_COMMIT();
    load_stage(1, 1); CP_COMMIT();
    load_stage(2, 2); CP_COMMIT();

    for (int k = 0; k < NKC; k++) {
        CP_WAIT(2);
        __syncthreads();                    // stage k visible; buf (k+3)&3 free
        if (k + 3 < NKC) load_stage((k + 3) & 3, k + 3);
        CP_COMMIT();

        uint32_t s0 = sb + (k & 3) * STG;
        #pragma unroll
        for (int ks = 0; ks < 2; ks++) {
            uint32_t ahf[2][4], alf[2][4], bhf[2][4], blf[2][4];
            #pragma unroll
            for (int mi = 0; mi < 2; mi++) {
                uint32_t off = (uint32_t)((wm * 32 + mi * 16 + (lane & 15)) * 64
                                          + ks * 32 + ((lane >> 4) << 4));
                off = sw64(off);
                ldm4(ahf[mi], s0 + A_H + off);
                ldm4(alf[mi], s0 + A_L + off);
            }
            #pragma unroll
            for (int nj = 0; nj < 2; nj++) {
                int rr = wn * 32 + nj * 16 + (lane & 7) + ((lane >> 4) << 3);
                uint32_t off = (uint32_t)(rr * 64 + ks * 32 + (((lane >> 3) & 1) << 4));
                off = sw64(off);
                ldm4(bhf[nj], s0 + B_H + off);
                ldm4(blf[nj], s0 + B_L + off);
            }
            #pragma unroll
            for (int mi = 0; mi < 2; mi++)
                #pragma unroll
                for (int ni = 0; ni < 4; ni++) {
                    const uint32_t* bh2 = &bhf[ni >> 1][(ni & 1) * 2];
                    const uint32_t* bl2 = &blf[ni >> 1][(ni & 1) * 2];
                    mma_bf16(acc[mi][ni], ahf[mi], bh2[0], bh2[1]);
                    mma_bf16(acc[mi][ni], ahf[mi], bl2[0], bl2[1]);
                    mma_bf16(acc[mi][ni], alf[mi], bh2[0], bh2[1]);
                }
        }
    }

    // epilogue
    #pragma unroll
    for (int mi = 0; mi < 2; mi++) {
        int r0 = bm + wm * 32 + mi * 16 + (lane >> 2);
        #pragma unroll
        for (int ni = 0; ni < 4; ni++) {
            int col = bn + wn * 32 + ni * 8 + ((lane & 3) << 1);
            float bb0 = bias[col], bb1 = bias[col + 1];
            float v00 = acc[mi][ni][0] + bb0, v01 = acc[mi][ni][1] + bb1;
            float v10 = acc[mi][ni][2] + bb0, v11 = acc[mi][ni][3] + bb1;
            if (EPI == 1) {
                v00 = fmaxf(v00, 0.f); v01 = fmaxf(v01, 0.f);
                v10 = fmaxf(v10, 0.f); v11 = fmaxf(v11, 0.f);
                __nv_bfloat162* oh = (__nv_bfloat162*)O1;
                __nv_bfloat162* ol = (__nv_bfloat162*)O2;
                __nv_bfloat16 h00 = __float2bfloat16(v00), h01 = __float2bfloat16(v01);
                __nv_bfloat16 h10 = __float2bfloat16(v10), h11 = __float2bfloat16(v11);
                __nv_bfloat162 t0; t0.x = h00; t0.y = h01;
                __nv_bfloat162 t1; t1.x = h10; t1.y = h11;
                __nv_bfloat162 u0; u0.x = __float2bfloat16(v00 - __bfloat162float(h00));
                                   u0.y = __float2bfloat16(v01 - __bfloat162float(h01));
                __nv_bfloat162 u1; u1.x = __float2bfloat16(v10 - __bfloat162float(h10));
                                   u1.y = __float2bfloat16(v11 - __bfloat162float(h11));
                oh[((size_t)r0 * NP + col) >> 1] = t0;
                oh[((size_t)(r0 + 8) * NP + col) >> 1] = t1;
                ol[((size_t)r0 * NP + col) >> 1] = u0;
                ol[((size_t)(r0 + 8) * NP + col) >> 1] = u1;
            } else {
                float2* o = (float2*)O1;
                float2 f0; f0.x = v00; f0.y = v01;
                float2 f1; f1.x = v10; f1.y = v11;
                o[((size_t)r0 * NP + col) >> 1] = f0;
                o[((size_t)(r0 + 8) * NP + col) >> 1] = f1;
                float m0 = (r0 < NN) ? 1.f : 0.f;
                float m1 = (r0 + 8 < NN) ? 1.f : 0.f;
                float s0 = m0 * v00 + m1 * v10;
                float s1 = m0 * v01 + m1 * v11;
                float q0 = m0 * v00 * v00 + m1 * v10 * v10;
                float q1 = m0 * v01 * v01 + m1 * v11 * v11;
                #pragma unroll
                for (int d = 4; d < 32; d <<= 1) {
                    s0 += __shfl_xor_sync(0xffffffff, s0, d);
                    s1 += __shfl_xor_sync(0xffffffff, s1, d);
                    q0 += __shfl_xor_sync(0xffffffff, q0, d);
                    q1 += __shfl_xor_sync(0xffffffff, q1, d);
                }
                if (lane < 4) {
                    int cl = wn * 32 + ni * 8 + ((lane & 3) << 1);
                    atomicAdd(&sstat[cl], s0);
                    atomicAdd(&sstat[cl + 1], s1);
                    atomicAdd(&sstat[64 + cl], q0);
                    atomicAdd(&sstat[64 + cl + 1], q1);
                }
            }
        }
    }
    if (EPI == 2) {
        __syncthreads();
        if (tid < 64) {
            int c = bn + tid;
            if (c < EMB) {
                atomicAdd(&stats[c], sstat[tid]);
                atomicAdd(&stats[EMB + c], sstat[64 + tid]);
            }
        }
    }
}

// ================= CSR build =================
__global__ void k_csr_zero(int* __restrict__ deg) {
    int i = blockIdx.x * blockDim.x + threadIdx.x;
    if (i < NN) deg[i] = 0;
}
__global__ void k_csr_hist(const int* __restrict__ ei, int* __restrict__ deg) {
    int e = blockIdx.x * blockDim.x + threadIdx.x;
    if (e < NE) atomicAdd(&deg[ei[NE + e]], 1);
}
__global__ void k_scan1(const int* __restrict__ deg, int* __restrict__ rowptr,
                        int* __restrict__ bsum) {
    __shared__ int sh[256];
    int t = threadIdx.x;
    int i = blockIdx.x * 256 + t;
    int v = (i < NN) ? deg[i] : 0;
    sh[t] = v;
    __syncthreads();
    #pragma unroll
    for (int off = 1; off < 256; off <<= 1) {
        int x = (t >= off) ? sh[t - off] : 0;
        __syncthreads();
        if (t >= off) sh[t] += x;
        __syncthreads();
    }
    if (i < NN) rowptr[i] = sh[t] - v;
    if (t == 255) bsum[blockIdx.x] = sh[255];
}
__global__ void k_scan2(const int* __restrict__ bsum, int* __restrict__ boff) {
    __shared__ int sh[128];
    int t = threadIdx.x;
    int v = (t < NB_SCAN) ? bsum[t] : 0;
    sh[t] = v;
    __syncthreads();
    #pragma unroll
    for (int off = 1; off < 128; off <<= 1) {
        int x = (t >= off) ? sh[t - off] : 0;
        __syncthreads();
        if (t >= off) sh[t] += x;
        __syncthreads();
    }
    if (t < NB_SCAN) boff[t] = sh[t] - v;
}
__global__ void k_scan3(int* __restrict__ rowptr, const int* __restrict__ boff,
                        int* __restrict__ cursor) {
    int i = blockIdx.x * blockDim.x + threadIdx.x;
    if (i < NN) {
        int r = rowptr[i] + boff[i >> 8];
        rowptr[i] = r;
        cursor[i] = r;
    }
    if (i == 0) rowptr[NN] = NE;
}
__global__ void k_fill(const int* __restrict__ ei, const int* __restrict__ ea,
                       int* __restrict__ cursor, int* __restrict__ csr) {
    int e = blockIdx.x * blockDim.x + threadIdx.x;
    if (e < NE) {
        int d = ei[NE + e];
        int p = atomicAdd(&cursor[d], 1);
        csr[p] = ei[e] | (ea[2 * e] << 16) | (ea[2 * e + 1] << 20);
    }
}

// ================= gather aggregate (warp per node), edge loop unrolled x2 ===========
template <bool BN>
__global__ void __launch_bounds__(256)
k_gather(const int* __restrict__ csr, const int* __restrict__ rowptr,
         const float* __restrict__ e1l, const float* __restrict__ e2l,
         const float* __restrict__ hbuf,
         const float* __restrict__ stats, const float* __restrict__ gamma,
         const float* __restrict__ beta,
         __nv_bfloat16* __restrict__ ah, __nv_bfloat16* __restrict__ al)
{
    int v = (blockIdx.x * blockDim.x + threadIdx.x) >> 5;
    int lane = threadIdx.x & 31;
    if (v >= NN) return;

    const int c0 = lane, c1 = lane + 32, c2 = lane + 64;   // float4 chunks
    const bool has2 = (c2 < 75);

    float4 A0, B0, A1, B1, A2, B2;
    if (BN) {
        const float inv_n = 1.f / NN;
        const float4* sS = (const float4*)stats;
        const float4* sQ = (const float4*)(stats + EMB);
        const float4* sG = (const float4*)gamma;
        const float4* sB = (const float4*)beta;
        auto coef = [&](int c, float4& A, float4& B) {
            float4 s = sS[c], q = sQ[c], g = sG[c], be = sB[c];
            float m, var;
            m = s.x * inv_n; var = q.x * inv_n - m * m; A.x = g.x * rsqrtf(var + 1e-5f); B.x = be.x - m * A.x;
            m = s.y * inv_n; var = q.y * inv_n - m * m; A.y = g.y * rsqrtf(var + 1e-5f); B.y = be.y - m * A.y;
            m = s.z * inv_n; var = q.z * inv_n - m * m; A.z = g.z * rsqrtf(var + 1e-5f); B.z = be.z - m * A.z;
            m = s.w * inv_n; var = q.w * inv_n - m * m; A.w = g.w * rsqrtf(var + 1e-5f); B.w = be.w - m * A.w;
        };
        coef(c0, A0, B0);
        coef(c1, A1, B1);
        if (has2) coef(c2, A2, B2);
    }

    auto bnr = [&](float4 x, const float4& A, const float4& B) {
        if (!BN) return x;
        float4 y;
        y.x = fmaxf(fmaf(A.x, x.x, B.x), 0.f);
        y.y = fmaxf(fmaf(A.y, x.y, B.y), 0.f);
        y.z = fmaxf(fmaf(A.z, x.z, B.z), 0.f);
        y.w = fmaxf(fmaf(A.w, x.w, B.w), 0.f);
        return y;
    };

    float4 f0, f1, f2;
    {
        const float4* hv = (const float4*)(hbuf + (size_t)v * EMBP);
        f0 = bnr(hv[c0], A0, B0);
        f1 = bnr(hv[c1], A1, B1);
        f2 = has2 ? bnr(hv[c2], A2, B2) : make_float4(0.f, 0.f, 0.f, 0.f);
    }
    int n10 = 0, n11 = 0, n12 = 0, n13 = 0, n14 = 1, n15 = 0;
    int n20 = 1, n21 = 0, n22 = 0;

    int s = rowptr[v], e = rowptr[v + 1];
    int p = s;
    // ---- unrolled x2: two distinct register sets so two edges' loads overlap ----
    for (; p + 2 <= e; p += 2) {
        int wa = csr[p], wb = csr[p + 1];
        const float4* ra = (const float4*)(hbuf + (size_t)(wa & 0xFFFF) * EMBP);
        const float4* rb = (const float4*)(hbuf + (size_t)(wb & 0xFFFF) * EMBP);
        // issue all loads first
        float4 xa0 = ra[c0], xb0 = rb[c0];
        float4 xa1 = ra[c1], xb1 = rb[c1];
        float4 xa2, xb2;
        if (has2) { xa2 = ra[c2]; xb2 = rb[c2]; }
        {
            int a0 = (wa >> 16) & 15, a1 = wa >> 20;
            n10 += (a0 == 0); n11 += (a0 == 1); n12 += (a0 == 2);
            n13 += (a0 == 3); n14 += (a0 == 4); n15 += (a0 == 5);
            n20 += (a1 == 0); n21 += (a1 == 1); n22 += (a1 == 2);
            a0 = (wb >> 16) & 15; a1 = wb >> 20;
            n10 += (a0 == 0); n11 += (a0 == 1); n12 += (a0 == 2);
            n13 += (a0 == 3); n14 += (a0 == 4); n15 += (a0 == 5);
            n20 += (a1 == 0); n21 += (a1 == 1); n22 += (a1 == 2);
        }
        xa0 = bnr(xa0, A0, B0); xb0 = bnr(xb0, A0, B0);
        xa1 = bnr(xa1, A1, B1); xb1 = bnr(xb1, A1, B1);
        f0.x += xa0.x + xb0.x; f0.y += xa0.y + xb0.y; f0.z += xa0.z + xb0.z; f0.w += xa0.w + xb0.w;
        f1.x += xa1.x + xb1.x; f1.y += xa1.y + xb1.y; f1.z += xa1.z + xb1.z; f1.w += xa1.w + xb1.w;
        if (has2) {
            xa2 = bnr(xa2, A2, B2); xb2 = bnr(xb2, A2, B2);
            f2.x += xa2.x + xb2.x; f2.y += xa2.y + xb2.y; f2.z += xa2.z + xb2.z; f2.w += xa2.w + xb2.w;
        }
    }
    if (p < e) {
        int w = csr[p];
        int src = w & 0xFFFF;
        int a0 = (w >> 16) & 15, a1 = w >> 20;
        n10 += (a0 == 0); n11 += (a0 == 1); n12 += (a0 == 2);
        n13 += (a0 == 3); n14 += (a0 == 4); n15 += (a0 == 5);
        n20 += (a1 == 0); n21 += (a1 == 1); n22 += (a1 == 2);
        const float4* hs = (const float4*)(hbuf + (size_t)src * EMBP);
        float4 x0 = bnr(hs[c0], A0, B0);
        float4 x1 = bnr(hs[c1], A1, B1);
        f0.x += x0.x; f0.y += x0.y; f0.z += x0.z; f0.w += x0.w;
        f1.x += x1.x; f1.y += x1.y; f1.z += x1.z; f1.w += x1.w;
        if (has2) {
            float4 x2 = bnr(hs[c2], A2, B2);
            f2.x += x2.x; f2.y += x2.y; f2.z += x2.z; f2.w += x2.w;
        }
    }

    auto addw = [&](const float* row, float wgt) {
        const float4* t = (const float4*)row;
        float4 x0 = t[c0], x1 = t[c1];
        f0.x += wgt * x0.x; f0.y += wgt * x0.y; f0.z += wgt * x0.z; f0.w += wgt * x0.w;
        f1.x += wgt * x1.x; f1.y += wgt * x1.y; f1.z += wgt * x1.z; f1.w += wgt * x1.w;
        if (has2) {
            float4 x2 = t[c2];
            f2.x += wgt * x2.x; f2.y += wgt * x2.y; f2.z += wgt * x2.z; f2.w += wgt * x2.w;
        }
    };
    if (n10) addw(e1l + 0 * EMB, (float)n10);
    if (n11) addw(e1l + 1 * EMB, (float)n11);
    if (n12) addw(e1l + 2 * EMB, (float)n12);
    if (n13) addw(e1l + 3 * EMB, (float)n13);
    if (n14) addw(e1l + 4 * EMB, (float)n14);
    if (n15) addw(e1l + 5 * EMB, (float)n15);
    if (n20) addw(e2l + 0 * EMB, (float)n20);
    if (n21) addw(e2l + 1 * EMB, (float)n21);
    if (n22) addw(e2l + 2 * EMB, (float)n22);

    auto wr = [&](int c, float4 f) {
        __nv_bfloat16 h0 = __float2bfloat16(f.x), h1 = __float2bfloat16(f.y);
        __nv_bfloat16 h2b = __float2bfloat16(f.z), h3 = __float2bfloat16(f.w);
        __nv_bfloat162 p0; p0.x = h0;  p0.y = h1;
        __nv_bfloat162 p1; p1.x = h2b; p1.y = h3;
        __nv_bfloat162 q0; q0.x = __float2bfloat16(f.x - __bfloat162float(h0));
                           q0.y = __float2bfloat16(f.y - __bfloat162float(h1));
        __nv_bfloat162 q1; q1.x = __float2bfloat16(f.z - __bfloat162float(h2b));
                           q1.y = __float2bfloat16(f.w - __bfloat162float(h3));
        size_t base = ((size_t)v * EMBP + 4 * c) >> 1;
        ((__nv_bfloat162*)ah)[base] = p0;
        ((__nv_bfloat162*)ah)[base + 1] = p1;
        ((__nv_bfloat162*)al)[base] = q0;
        ((__nv_bfloat162*)al)[base + 1] = q1;
    };
    wr(c0, f0);
    wr(c1, f1);
    if (has2) wr(c2, f2);
}

// ================= misc kernels =================
// vectorized init: thread = one float4 chunk (75 per row)
__global__ void k_init(const int* __restrict__ x,
                       const float* __restrict__ xe1,
                       const float* __restrict__ xe2,
                       float* __restrict__ h) {
    int idx = blockIdx.x * blockDim.x + threadIdx.x;
    if (idx >= NN * 75) return;
    int i = idx / 75;
    int c = idx - i * 75;
    int x0 = x[2 * i], x1 = x[2 * i + 1];
    float4 u = ((const float4*)(xe1 + (size_t)x0 * EMB))[c];
    float4 w = ((const float4*)(xe2 + (size_t)x1 * EMB))[c];
    float4 r;
    r.x = u.x + w.x; r.y = u.y + w.y; r.z = u.z + w.z; r.w = u.w + w.w;
    ((float4*)(h + (size_t)i * EMBP))[c] = r;
}

// Tiled transpose + split: W [K,N] row-major -> WT hi/lo [NP,KP] (zero-padded)
__global__ void k_prepw(const float* __restrict__ W,
                        __nv_bfloat16* __restrict__ wh, __nv_bfloat16* __restrict__ wl,
                        int K, int N, int KP, int NP) {
    __shared__ float sm[32][33];
    int l = blockIdx.z;
    const float* Wl = W + (size_t)l * K * N;
    __nv_bfloat16* whl = wh + (size_t)l * NP * KP;
    __nv_bfloat16* wll = wl + (size_t)l * NP * KP;
    int n0 = blockIdx.x * 32, k0 = blockIdx.y * 32;
    int tx = threadIdx.x, ty = threadIdx.y;    // 32 x 8
    #pragma unroll
    for (int s = 0; s < 4; s++) {
        int k = k0 + ty + 8 * s;
        int n = n0 + tx;
        sm[ty + 8 * s][tx] = (k < K && n < N) ? Wl[(size_t)k * N + n] : 0.f;
    }
    __syncthreads();
    #pragma unroll
    for (int s = 0; s < 4; s++) {
        int n = n0 + ty + 8 * s;
        int k = k0 + tx;
        float v = sm[tx][ty + 8 * s];
        __nv_bfloat16 h = __float2bfloat16(v);
        whl[(size_t)n * KP + k] = h;
        wll[(size_t)n * KP + k] = __float2bfloat16(v - __bfloat162float(h));
    }
}

__global__ void k_prepb(const float* __restrict__ b1, const float* __restrict__ b2,
                        float* __restrict__ b1p, float* __restrict__ b2p) {
    int idx = blockIdx.x * blockDim.x + threadIdx.x;
    if (idx < NL * HIDP) {
        int l = idx / HIDP, j = idx - l * HIDP;
        b1p[idx] = (j < HID) ? b1[l * HID + j] : 0.f;
    }
    if (idx < NL * EMBP) {
        int l = idx / EMBP, j = idx - l * EMBP;
        b2p[idx] = (j < EMB) ? b2[l * EMB + j] : 0.f;
    }
}

// vectorized final BN: thread = one float4 chunk (75 per row)
__global__ void k_bnapply(const float* __restrict__ h2,
                          const float* __restrict__ gamma, const float* __restrict__ beta,
                          const float* __restrict__ stats,
                          float* __restrict__ dst) {
    int idx = blockIdx.x * blockDim.x + threadIdx.x;
    if (idx >= NN * 75) return;
    int r = idx / 75;
    int c = idx - r * 75;
    const float inv_n = 1.f / NN;
    float4 s = ((const float4*)stats)[c];
    float4 q = ((const float4*)(stats + EMB))[c];
    float4 g = ((const float4*)gamma)[c];
    float4 be = ((const float4*)beta)[c];
    float4 xv = ((const float4*)(h2 + (size_t)r * EMBP))[c];
    float4 y;
    float m, var;
    m = s.x * inv_n; var = q.x * inv_n - m * m; y.x = (xv.x - m) * rsqrtf(var + 1e-5f) * g.x + be.x;
    m = s.y * inv_n; var = q.y * inv_n - m * m; y.y = (xv.y - m) * rsqrtf(var + 1e-5f) * g.y + be.y;
    m = s.z * inv_n; var = q.z * inv_n - m * m; y.z = (xv.z - m) * rsqrtf(var + 1e-5f) * g.z + be.z;
    m = s.w * inv_n; var = q.w * inv_n - m * m; y.w = (xv.w - m) * rsqrtf(var + 1e-5f) * g.w + be.w;
    ((float4*)(dst + (size_t)r * EMB))[c] = y;
}

// ================= launch =================
extern "C" void kernel_launch(void* const* d_in, const int* in_sizes, int n_in,
                              void* d_out, int out_size) {
    const int*   x     = (const int*)d_in[0];
    const int*   ei    = (const int*)d_in[1];
    const int*   ea    = (const int*)d_in[2];
    const float* xe1   = (const float*)d_in[3];
    const float* xe2   = (const float*)d_in[4];
    const float* e1    = (const float*)d_in[5];
    const float* e2    = (const float*)d_in[6];
    const float* W1    = (const float*)d_in[7];
    const float* b1    = (const float*)d_in[8];
    const float* W2    = (const float*)d_in[9];
    const float* b2    = (const float*)d_in[10];
    const float* gamma = (const float*)d_in[11];
    const float* beta  = (const float*)d_in[12];
    float* out = (float*)d_out;

    float *h, *h2, *b1p, *b2p, *stats;
    __nv_bfloat16 *ah, *al, *t1h, *t1l, *w1th, *w1tl, *w2th, *w2tl;
    int *deg, *rowptr, *cursor, *bsum, *boff, *csr;
    cudaGetSymbolAddress((void**)&h, g_h);
    cudaGetSymbolAddress((void**)&h2, g_h2);
    cudaGetSymbolAddress((void**)&ah, g_ah);
    cudaGetSymbolAddress((void**)&al, g_al);
    cudaGetSymbolAddress((void**)&t1h, g_t1h);
    cudaGetSymbolAddress((void**)&t1l, g_t1l);
    cudaGetSymbolAddress((void**)&w1th, g_w1th);
    cudaGetSymbolAddress((void**)&w1tl, g_w1tl);
    cudaGetSymbolAddress((void**)&w2th, g_w2th);
    cudaGetSymbolAddress((void**)&w2tl, g_w2tl);
    cudaGetSymbolAddress((void**)&b1p, g_b1p);
    cudaGetSymbolAddress((void**)&b2p, g_b2p);
    cudaGetSymbolAddress((void**)&stats, g_stats);
    cudaGetSymbolAddress((void**)&deg, g_deg);
    cudaGetSymbolAddress((void**)&rowptr, g_rowptr);
    cudaGetSymbolAddress((void**)&cursor, g_cursor);
    cudaGetSymbolAddress((void**)&bsum, g_bsum);
    cudaGetSymbolAddress((void**)&boff, g_boff);
    cudaGetSymbolAddress((void**)&csr, g_csr);

    const int SMEMSZ = 4 * 24576;  // 96KB -> 2 CTAs/SM
    cudaFuncSetAttribute((const void*)k_gemm<EMBP, EMBP, HIDP, 1>,
                         cudaFuncAttributeMaxDynamicSharedMemorySize, SMEMSZ);
    cudaFuncSetAttribute((const void*)k_gemm<HIDP, HIDE, EMBP, 2>,
                         cudaFuncAttributeMaxDynamicSharedMemorySize, SMEMSZ);

    const int TP = 256;

    // one-time prep (tiled transposes)
    {
        dim3 thr(32, 8);
        dim3 g1(HIDP / 32, EMBP / 32, NL);   // W1: K=EMB,N=HID -> [HIDP, EMBP]
        dim3 g2(EMBP / 32, HIDP / 32, NL);   // W2: K=HID,N=EMB -> [EMBP, HIDP]
        k_prepw<<<g1, thr>>>(W1, w1th, w1tl, EMB, HID, EMBP, HIDP);
        k_prepw<<<g2, thr>>>(W2, w2th, w2tl, HID, EMB, HIDP, EMBP);
    }
    k_prepb<<<(NL * HIDP + TP - 1) / TP, TP>>>(b1, b2, b1p, b2p);
    k_init<<<(NN * 75 + TP - 1) / TP, TP>>>(x, xe1, xe2, h);

    // CSR build
    k_csr_zero<<<(NN + TP - 1) / TP, TP>>>(deg);
    k_csr_hist<<<(NE + TP - 1) / TP, TP>>>(ei, deg);
    k_scan1<<<NB_SCAN, 256>>>(deg, rowptr, bsum);
    k_scan2<<<1, 128>>>(bsum, boff);
    k_scan3<<<(NN + TP - 1) / TP, TP>>>(rowptr, boff, cursor);
    k_fill<<<(NE + TP - 1) / TP, TP>>>(ei, ea, cursor, csr);

    const int gGather = (NN * 32 + TP - 1) / TP;

    for (int l = 0; l < NL; l++) {
        if (l == 0) {
            k_gather<false><<<gGather, TP>>>(csr, rowptr,
                                             e1, e2, h,
                                             nullptr, nullptr, nullptr, ah, al);
        } else {
            k_gather<true><<<gGather, TP>>>(csr, rowptr,
                                            e1 + (size_t)l * 6 * EMB,
                                            e2 + (size_t)l * 3 * EMB, h2,
                                            stats,
                                            gamma + (size_t)(l - 1) * EMB,
                                            beta + (size_t)(l - 1) * EMB, ah, al);
        }

        k_gemm<EMBP, EMBP, HIDP, 1><<<dim3(HIDP / 64, MP / 128), 256, SMEMSZ>>>(
            ah, al,
            w1th + (size_t)l * HIDP * EMBP, w1tl + (size_t)l * HIDP * EMBP,
            b1p + l * HIDP, t1h, t1l, stats);

        k_gemm<HIDP, HIDE, EMBP, 2><<<dim3(EMBP / 64, MP / 128), 256, SMEMSZ>>>(
            t1h, t1l,
            w2th + (size_t)l * EMBP * HIDP, w2tl + (size_t)l * EMBP * HIDP,
            b2p + l * EMBP, h2, nullptr, stats);
    }

    // final BN (no relu) -> out (vectorized)
    k_bnapply<<<(NN * 75 + TP - 1) / TP, TP>>>(h2, gamma + (size_t)(NL - 1) * EMB,
                                               beta + (size_t)(NL - 1) * EMB, stats, out);
}

// round 14
// speedup vs baseline: 1.0459x; 1.0459x over previous
#include <cuda_runtime.h>
#include <cuda_bf16.h>
#include <cstdint>

#define NN    30000
#define MP    30080          // rows padded to 235*128
#define NE    240000
#define EMB   300
#define EMBP  320            // padded emb
#define HID   600
#define HIDP  640            // padded hidden (stride)
#define HIDE  608            // effective K for GEMM2 (cols 608..639 of t1 are exact zeros)
#define NL    5
#define NB_SCAN 118          // ceil(30000/256)

// ---------------- scratch (device globals: allocation-free, zero-init) ----------------
__device__ float          g_h  [(size_t)NN * EMBP];     // layer-0 features only
__device__ float          g_h2 [(size_t)MP * EMBP];     // raw GEMM2 output (pre-BN)
__device__ __nv_bfloat16  g_ah [(size_t)MP * EMBP];     // pad rows/cols stay 0
__device__ __nv_bfloat16  g_al [(size_t)MP * EMBP];
__device__ __nv_bfloat16  g_t1h[(size_t)MP * HIDP];
__device__ __nv_bfloat16  g_t1l[(size_t)MP * HIDP];
__device__ __nv_bfloat16  g_w1th[(size_t)NL * HIDP * EMBP]; // W1^T split [l][n=640][k=320]
__device__ __nv_bfloat16  g_w1tl[(size_t)NL * HIDP * EMBP];
__device__ __nv_bfloat16  g_w2th[(size_t)NL * EMBP * HIDP]; // W2^T split [l][n=320][k=640]
__device__ __nv_bfloat16  g_w2tl[(size_t)NL * EMBP * HIDP];
__device__ float          g_b1p[NL * HIDP];
__device__ float          g_b2p[NL * EMBP];
__device__ float          g_stats[2 * EMB];
// CSR scratch
__device__ int            g_deg[NN];
__device__ int            g_rowptr[NN + 1];
__device__ int            g_cursor[NN];
__device__ int            g_bsum[NB_SCAN];
__device__ int            g_boff[NB_SCAN];
__device__ int            g_csr[NE];     // packed: src | a0<<16 | a1<<20

// ================= PTX helpers =================
__device__ __forceinline__ uint32_t smem_u32(const void* p) {
    uint32_t a;
    asm("{ .reg .u64 t; cvta.to.shared.u64 t, %1; cvt.u32.u64 %0, t; }" : "=r"(a) : "l"(p));
    return a;
}
__device__ __forceinline__ void cpa16(uint32_t s, const void* g) {
    asm volatile("cp.async.cg.shared.global [%0], [%1], 16;" :: "r"(s), "l"(g) : "memory");
}
#define CP_COMMIT() asm volatile("cp.async.commit_group;" ::: "memory")
#define CP_WAIT(n)  asm volatile("cp.async.wait_group %0;" :: "n"(n) : "memory")

__device__ __forceinline__ void ldm4(uint32_t* r, uint32_t a) {
    asm volatile("ldmatrix.sync.aligned.m8n8.x4.shared.b16 {%0,%1,%2,%3}, [%4];"
                 : "=r"(r[0]), "=r"(r[1]), "=r"(r[2]), "=r"(r[3]) : "r"(a));
}
__device__ __forceinline__ void mma_bf16(float* c, const uint32_t* a, uint32_t b0, uint32_t b1) {
    asm volatile(
        "mma.sync.aligned.m16n8k16.row.col.f32.bf16.bf16.f32 "
        "{%0,%1,%2,%3}, {%4,%5,%6,%7}, {%8,%9}, {%0,%1,%2,%3};"
        : "+f"(c[0]), "+f"(c[1]), "+f"(c[2]), "+f"(c[3])
        : "r"(a[0]), "r"(a[1]), "r"(a[2]), "r"(a[3]), "r"(b0), "r"(b1));
}

// SW64 swizzle for 64-byte rows
__device__ __forceinline__ uint32_t sw64(uint32_t off) {
    return off ^ ((off >> 3) & 0x30);
}

// ================= HMMA GEMM (bf16x3 split) — R7/R11 config, frozen =================
// CTA tile 128x64, 8 warps (4M x 2N), warp tile 32x32.
// K-chunk 32, 4-stage cp.async pipeline (24KB/stage, 96KB total -> 2 CTAs/SM).
// KP = row stride (elements); KEFF = contracted K (KEFF <= KP, multiple of 32).
// EPI==1: relu(acc+bias) -> split bf16 to O1/O2 (row stride NP); block(0,0) zeroes stats
// EPI==2: acc+bias -> f32 O1 (row stride NP), fused BN column sum/sumsq into stats
template <int KP, int KEFF, int NP, int EPI>
__global__ void __launch_bounds__(256, 2)
k_gemm(const __nv_bfloat16* __restrict__ Ah, const __nv_bfloat16* __restrict__ Al,
       const __nv_bfloat16* __restrict__ Bh, const __nv_bfloat16* __restrict__ Bl,
       const float* __restrict__ bias, void* __restrict__ O1, void* __restrict__ O2,
       float* __restrict__ stats)
{
    constexpr int NKC = KEFF / 32;
    constexpr uint32_t STG = 24576;
    constexpr uint32_t A_H = 0, A_L = 8192, B_H = 16384, B_L = 20480;

    __shared__ float sstat[128];        // [0:64) col sums, [64:128) col sumsqs

    extern __shared__ char smem[];
    const uint32_t sb = smem_u32(smem);
    const int tid  = threadIdx.x;
    const int lane = tid & 31;
    const int warp = tid >> 5;
    const int wm   = warp & 3;           // 0..3 (M)
    const int wn   = warp >> 2;          // 0..1 (N)
    const int bm   = blockIdx.y * 128;
    const int bn   = blockIdx.x * 64;

    if (EPI == 1 && blockIdx.x == 0 && blockIdx.y == 0) {
        for (int i = tid; i < 2 * EMB; i += 256) stats[i] = 0.f;
    }
    if (EPI == 2 && tid < 128) sstat[tid] = 0.f;

    const size_t rs = (size_t)KP * 2;    // row stride bytes

    auto load_stage = [&](int buf, int kc) {
        uint32_t s0 = sb + buf * STG;
        int k0 = kc * 32;
        const char* ahp = (const char*)(Ah + (size_t)bm * KP + k0);
        const char* alp = (const char*)(Al + (size_t)bm * KP + k0);
        const char* bhp = (const char*)(Bh + (size_t)bn * KP + k0);
        const char* blp = (const char*)(Bl + (size_t)bn * KP + k0);
        #pragma unroll
        for (int i = 0; i < 2; i++) {       // A: 128 rows x 4 x 16B = 512 chunks/half
            int idx = tid + 256 * i;
            int r = idx >> 2, c = (idx & 3) * 16;
            uint32_t sw = sw64((uint32_t)(r * 64 + c));
            cpa16(s0 + A_H + sw, ahp + (size_t)r * rs + c);
            cpa16(s0 + A_L + sw, alp + (size_t)r * rs + c);
        }
        {                                   // B: 64 rows x 4 x 16B = 256 chunks/half
            int r = tid >> 2, c = (tid & 3) * 16;
            uint32_t sw = sw64((uint32_t)(r * 64 + c));
            cpa16(s0 + B_H + sw, bhp + (size_t)r * rs + c);
            cpa16(s0 + B_L + sw, blp + (size_t)r * rs + c);
        }
    };

    float acc[2][4][4];
    #pragma unroll
    for (int mi = 0; mi < 2; mi++)
        #pragma unroll
        for (int ni = 0; ni < 4; ni++)
            #pragma unroll
            for (int q = 0; q < 4; q++) acc[mi][ni][q] = 0.f;

    load_stage(0, 0); CP_COMMIT();
    load_stage(1, 1); CP_COMMIT();
    load_stage(2, 2); CP_COMMIT();

    for (int k = 0; k < NKC; k++) {
        CP_WAIT(2);
        __syncthreads();                    // stage k visible; buf (k+3)&3 free
        if (k + 3 < NKC) load_stage((k + 3) & 3, k + 3);
        CP_COMMIT();

        uint32_t s0 = sb + (k & 3) * STG;
        #pragma unroll
        for (int ks = 0; ks < 2; ks++) {
            uint32_t ahf[2][4], alf[2][4], bhf[2][4], blf[2][4];
            #pragma unroll
            for (int mi = 0; mi < 2; mi++) {
                uint32_t off = (uint32_t)((wm * 32 + mi * 16 + (lane & 15)) * 64
                                          + ks * 32 + ((lane >> 4) << 4));
                off = sw64(off);
                ldm4(ahf[mi], s0 + A_H + off);
                ldm4(alf[mi], s0 + A_L + off);
            }
            #pragma unroll
            for (int nj = 0; nj < 2; nj++) {
                int rr = wn * 32 + nj * 16 + (lane & 7) + ((lane >> 4) << 3);
                uint32_t off = (uint32_t)(rr * 64 + ks * 32 + (((lane >> 3) & 1) << 4));
                off = sw64(off);
                ldm4(bhf[nj], s0 + B_H + off);
                ldm4(blf[nj], s0 + B_L + off);
            }
            #pragma unroll
            for (int mi = 0; mi < 2; mi++)
                #pragma unroll
                for (int ni = 0; ni < 4; ni++) {
                    const uint32_t* bh2 = &bhf[ni >> 1][(ni & 1) * 2];
                    const uint32_t* bl2 = &blf[ni >> 1][(ni & 1) * 2];
                    mma_bf16(acc[mi][ni], ahf[mi], bh2[0], bh2[1]);
                    mma_bf16(acc[mi][ni], ahf[mi], bl2[0], bl2[1]);
                    mma_bf16(acc[mi][ni], alf[mi], bh2[0], bh2[1]);
                }
        }
    }

    // epilogue
    #pragma unroll
    for (int mi = 0; mi < 2; mi++) {
        int r0 = bm + wm * 32 + mi * 16 + (lane >> 2);
        #pragma unroll
        for (int ni = 0; ni < 4; ni++) {
            int col = bn + wn * 32 + ni * 8 + ((lane & 3) << 1);
            float bb0 = bias[col], bb1 = bias[col + 1];
            float v00 = acc[mi][ni][0] + bb0, v01 = acc[mi][ni][1] + bb1;
            float v10 = acc[mi][ni][2] + bb0, v11 = acc[mi][ni][3] + bb1;
            if (EPI == 1) {
                v00 = fmaxf(v00, 0.f); v01 = fmaxf(v01, 0.f);
                v10 = fmaxf(v10, 0.f); v11 = fmaxf(v11, 0.f);
                __nv_bfloat162* oh = (__nv_bfloat162*)O1;
                __nv_bfloat162* ol = (__nv_bfloat162*)O2;
                __nv_bfloat16 h00 = __float2bfloat16(v00), h01 = __float2bfloat16(v01);
                __nv_bfloat16 h10 = __float2bfloat16(v10), h11 = __float2bfloat16(v11);
                __nv_bfloat162 t0; t0.x = h00; t0.y = h01;
                __nv_bfloat162 t1; t1.x = h10; t1.y = h11;
                __nv_bfloat162 u0; u0.x = __float2bfloat16(v00 - __bfloat162float(h00));
                                   u0.y = __float2bfloat16(v01 - __bfloat162float(h01));
                __nv_bfloat162 u1; u1.x = __float2bfloat16(v10 - __bfloat162float(h10));
                                   u1.y = __float2bfloat16(v11 - __bfloat162float(h11));
                oh[((size_t)r0 * NP + col) >> 1] = t0;
                oh[((size_t)(r0 + 8) * NP + col) >> 1] = t1;
                ol[((size_t)r0 * NP + col) >> 1] = u0;
                ol[((size_t)(r0 + 8) * NP + col) >> 1] = u1;
            } else {
                float2* o = (float2*)O1;
                float2 f0; f0.x = v00; f0.y = v01;
                float2 f1; f1.x = v10; f1.y = v11;
                o[((size_t)r0 * NP + col) >> 1] = f0;
                o[((size_t)(r0 + 8) * NP + col) >> 1] = f1;
                float m0 = (r0 < NN) ? 1.f : 0.f;
                float m1 = (r0 + 8 < NN) ? 1.f : 0.f;
                float s0 = m0 * v00 + m1 * v10;
                float s1 = m0 * v01 + m1 * v11;
                float q0 = m0 * v00 * v00 + m1 * v10 * v10;
                float q1 = m0 * v01 * v01 + m1 * v11 * v11;
                #pragma unroll
                for (int d = 4; d < 32; d <<= 1) {
                    s0 += __shfl_xor_sync(0xffffffff, s0, d);
                    s1 += __shfl_xor_sync(0xffffffff, s1, d);
                    q0 += __shfl_xor_sync(0xffffffff, q0, d);
                    q1 += __shfl_xor_sync(0xffffffff, q1, d);
                }
                if (lane < 4) {
                    int cl = wn * 32 + ni * 8 + ((lane & 3) << 1);
                    atomicAdd(&sstat[cl], s0);
                    atomicAdd(&sstat[cl + 1], s1);
                    atomicAdd(&sstat[64 + cl], q0);
                    atomicAdd(&sstat[64 + cl + 1], q1);
                }
            }
        }
    }
    if (EPI == 2) {
        __syncthreads();
        if (tid < 64) {
            int c = bn + tid;
            if (c < EMB) {
                atomicAdd(&stats[c], sstat[tid]);
                atomicAdd(&stats[EMB + c], sstat[64 + tid]);
            }
        }
    }
}

// ================= CSR build =================
__global__ void k_csr_hist(const int* __restrict__ ei, int* __restrict__ deg) {
    int e = blockIdx.x * blockDim.x + threadIdx.x;
    if (e < NE) atomicAdd(&deg[ei[NE + e]], 1);
}
__global__ void k_scan1(const int* __restrict__ deg, int* __restrict__ rowptr,
                        int* __restrict__ bsum) {
    __shared__ int sh[256];
    int t = threadIdx.x;
    int i = blockIdx.x * 256 + t;
    int v = (i < NN) ? deg[i] : 0;
    sh[t] = v;
    __syncthreads();
    #pragma unroll
    for (int off = 1; off < 256; off <<= 1) {
        int x = (t >= off) ? sh[t - off] : 0;
        __syncthreads();
        if (t >= off) sh[t] += x;
        __syncthreads();
    }
    if (i < NN) rowptr[i] = sh[t] - v;
    if (t == 255) bsum[blockIdx.x] = sh[255];
}
__global__ void k_scan2(const int* __restrict__ bsum, int* __restrict__ boff) {
    __shared__ int sh[128];
    int t = threadIdx.x;
    int v = (t < NB_SCAN) ? bsum[t] : 0;
    sh[t] = v;
    __syncthreads();
    #pragma unroll
    for (int off = 1; off < 128; off <<= 1) {
        int x = (t >= off) ? sh[t - off] : 0;
        __syncthreads();
        if (t >= off) sh[t] += x;
        __syncthreads();
    }
    if (t < NB_SCAN) boff[t] = sh[t] - v;
}
__global__ void k_scan3(int* __restrict__ rowptr, const int* __restrict__ boff,
                        int* __restrict__ cursor) {
    int i = blockIdx.x * blockDim.x + threadIdx.x;
    if (i < NN) {
        int r = rowptr[i] + boff[i >> 8];
        rowptr[i] = r;
        cursor[i] = r;
    }
    if (i == 0) rowptr[NN] = NE;
}
__global__ void k_fill(const int* __restrict__ ei, const int* __restrict__ ea,
                       int* __restrict__ cursor, int* __restrict__ csr) {
    int e = blockIdx.x * blockDim.x + threadIdx.x;
    if (e < NE) {
        int d = ei[NE + e];
        int p = atomicAdd(&cursor[d], 1);
        csr[p] = ei[e] | (ea[2 * e] << 16) | (ea[2 * e + 1] << 20);
    }
}

// ================= gather aggregate (warp per node) — R12 version, frozen ============
template <bool BN>
__global__ void __launch_bounds__(256)
k_gather(const int* __restrict__ csr, const int* __restrict__ rowptr,
         const float* __restrict__ e1l, const float* __restrict__ e2l,
         const float* __restrict__ hbuf,
         const float* __restrict__ stats, const float* __restrict__ gamma,
         const float* __restrict__ beta,
         __nv_bfloat16* __restrict__ ah, __nv_bfloat16* __restrict__ al)
{
    int v = (blockIdx.x * blockDim.x + threadIdx.x) >> 5;
    int lane = threadIdx.x & 31;
    if (v >= NN) return;

    const int c0 = lane, c1 = lane + 32, c2 = lane + 64;   // float4 chunks
    const bool has2 = (c2 < 75);

    float4 A0, B0, A1, B1, A2, B2;
    if (BN) {
        const float inv_n = 1.f / NN;
        const float4* sS = (const float4*)stats;
        const float4* sQ = (const float4*)(stats + EMB);
        const float4* sG = (const float4*)gamma;
        const float4* sB = (const float4*)beta;
        auto coef = [&](int c, float4& A, float4& B) {
            float4 s = sS[c], q = sQ[c], g = sG[c], be = sB[c];
            float m, var;
            m = s.x * inv_n; var = q.x * inv_n - m * m; A.x = g.x * rsqrtf(var + 1e-5f); B.x = be.x - m * A.x;
            m = s.y * inv_n; var = q.y * inv_n - m * m; A.y = g.y * rsqrtf(var + 1e-5f); B.y = be.y - m * A.y;
            m = s.z * inv_n; var = q.z * inv_n - m * m; A.z = g.z * rsqrtf(var + 1e-5f); B.z = be.z - m * A.z;
            m = s.w * inv_n; var = q.w * inv_n - m * m; A.w = g.w * rsqrtf(var + 1e-5f); B.w = be.w - m * A.w;
        };
        coef(c0, A0, B0);
        coef(c1, A1, B1);
        if (has2) coef(c2, A2, B2);
    }

    auto bnr = [&](float4 x, const float4& A, const float4& B) {
        if (!BN) return x;
        float4 y;
        y.x = fmaxf(fmaf(A.x, x.x, B.x), 0.f);
        y.y = fmaxf(fmaf(A.y, x.y, B.y), 0.f);
        y.z = fmaxf(fmaf(A.z, x.z, B.z), 0.f);
        y.w = fmaxf(fmaf(A.w, x.w, B.w), 0.f);
        return y;
    };

    float4 f0, f1, f2;
    {
        const float4* hv = (const float4*)(hbuf + (size_t)v * EMBP);
        f0 = bnr(hv[c0], A0, B0);
        f1 = bnr(hv[c1], A1, B1);
        f2 = has2 ? bnr(hv[c2], A2, B2) : make_float4(0.f, 0.f, 0.f, 0.f);
    }
    int n10 = 0, n11 = 0, n12 = 0, n13 = 0, n14 = 1, n15 = 0;
    int n20 = 1, n21 = 0, n22 = 0;

    int s = rowptr[v], e = rowptr[v + 1];
    for (int p = s; p < e; p++) {
        int w = csr[p];
        int src = w & 0xFFFF;
        int a0 = (w >> 16) & 15, a1 = w >> 20;
        n10 += (a0 == 0); n11 += (a0 == 1); n12 += (a0 == 2);
        n13 += (a0 == 3); n14 += (a0 == 4); n15 += (a0 == 5);
        n20 += (a1 == 0); n21 += (a1 == 1); n22 += (a1 == 2);
        const float4* hs = (const float4*)(hbuf + (size_t)src * EMBP);
        float4 x0 = bnr(hs[c0], A0, B0);
        float4 x1 = bnr(hs[c1], A1, B1);
        f0.x += x0.x; f0.y += x0.y; f0.z += x0.z; f0.w += x0.w;
        f1.x += x1.x; f1.y += x1.y; f1.z += x1.z; f1.w += x1.w;
        if (has2) {
            float4 x2 = bnr(hs[c2], A2, B2);
            f2.x += x2.x; f2.y += x2.y; f2.z += x2.z; f2.w += x2.w;
        }
    }
    auto addw = [&](const float* row, float wgt) {
        const float4* t = (const float4*)row;
        float4 x0 = t[c0], x1 = t[c1];
        f0.x += wgt * x0.x; f0.y += wgt * x0.y; f0.z += wgt * x0.z; f0.w += wgt * x0.w;
        f1.x += wgt * x1.x; f1.y += wgt * x1.y; f1.z += wgt * x1.z; f1.w += wgt * x1.w;
        if (has2) {
            float4 x2 = t[c2];
            f2.x += wgt * x2.x; f2.y += wgt * x2.y; f2.z += wgt * x2.z; f2.w += wgt * x2.w;
        }
    };
    if (n10) addw(e1l + 0 * EMB, (float)n10);
    if (n11) addw(e1l + 1 * EMB, (float)n11);
    if (n12) addw(e1l + 2 * EMB, (float)n12);
    if (n13) addw(e1l + 3 * EMB, (float)n13);
    if (n14) addw(e1l + 4 * EMB, (float)n14);
    if (n15) addw(e1l + 5 * EMB, (float)n15);
    if (n20) addw(e2l + 0 * EMB, (float)n20);
    if (n21) addw(e2l + 1 * EMB, (float)n21);
    if (n22) addw(e2l + 2 * EMB, (float)n22);

    auto wr = [&](int c, float4 f) {
        __nv_bfloat16 h0 = __float2bfloat16(f.x), h1 = __float2bfloat16(f.y);
        __nv_bfloat16 h2b = __float2bfloat16(f.z), h3 = __float2bfloat16(f.w);
        __nv_bfloat162 p0; p0.x = h0;  p0.y = h1;
        __nv_bfloat162 p1; p1.x = h2b; p1.y = h3;
        __nv_bfloat162 q0; q0.x = __float2bfloat16(f.x - __bfloat162float(h0));
                           q0.y = __float2bfloat16(f.y - __bfloat162float(h1));
        __nv_bfloat162 q1; q1.x = __float2bfloat16(f.z - __bfloat162float(h2b));
                           q1.y = __float2bfloat16(f.w - __bfloat162float(h3));
        size_t base = ((size_t)v * EMBP + 4 * c) >> 1;
        ((__nv_bfloat162*)ah)[base] = p0;
        ((__nv_bfloat162*)ah)[base + 1] = p1;
        ((__nv_bfloat162*)al)[base] = q0;
        ((__nv_bfloat162*)al)[base + 1] = q1;
    };
    wr(c0, f0);
    wr(c1, f1);
    if (has2) wr(c2, f2);
}

// ================= misc kernels =================
// vectorized init: thread = one float4 chunk (75 per row)
__global__ void k_init(const int* __restrict__ x,
                       const float* __restrict__ xe1,
                       const float* __restrict__ xe2,
                       float* __restrict__ h) {
    int idx = blockIdx.x * blockDim.x + threadIdx.x;
    if (idx >= NN * 75) return;
    int i = idx / 75;
    int c = idx - i * 75;
    int x0 = x[2 * i], x1 = x[2 * i + 1];
    float4 u = ((const float4*)(xe1 + (size_t)x0 * EMB))[c];
    float4 w = ((const float4*)(xe2 + (size_t)x1 * EMB))[c];
    float4 r;
    r.x = u.x + w.x; r.y = u.y + w.y; r.z = u.z + w.z; r.w = u.w + w.w;
    ((float4*)(h + (size_t)i * EMBP))[c] = r;
}

// Tiled transpose + split: W [K,N] row-major -> WT hi/lo [NP,KP] (zero-padded)
__global__ void k_prepw(const float* __restrict__ W,
                        __nv_bfloat16* __restrict__ wh, __nv_bfloat16* __restrict__ wl,
                        int K, int N, int KP, int NP) {
    __shared__ float sm[32][33];
    int l = blockIdx.z;
    const float* Wl = W + (size_t)l * K * N;
    __nv_bfloat16* whl = wh + (size_t)l * NP * KP;
    __nv_bfloat16* wll = wl + (size_t)l * NP * KP;
    int n0 = blockIdx.x * 32, k0 = blockIdx.y * 32;
    int tx = threadIdx.x, ty = threadIdx.y;    // 32 x 8
    #pragma unroll
    for (int s = 0; s < 4; s++) {
        int k = k0 + ty + 8 * s;
        int n = n0 + tx;
        sm[ty + 8 * s][tx] = (k < K && n < N) ? Wl[(size_t)k * N + n] : 0.f;
    }
    __syncthreads();
    #pragma unroll
    for (int s = 0; s < 4; s++) {
        int n = n0 + ty + 8 * s;
        int k = k0 + tx;
        float v = sm[tx][ty + 8 * s];
        __nv_bfloat16 h = __float2bfloat16(v);
        whl[(size_t)n * KP + k] = h;
        wll[(size_t)n * KP + k] = __float2bfloat16(v - __bfloat162float(h));
    }
}

// bias padding + CSR degree zeroing (fused; deg zero must precede k_csr_hist,
// which holds by stream order)
__global__ void k_prepb(const float* __restrict__ b1, const float* __restrict__ b2,
                        float* __restrict__ b1p, float* __restrict__ b2p,
                        int* __restrict__ deg) {
    int idx = blockIdx.x * blockDim.x + threadIdx.x;
    if (idx < NL * HIDP) {
        int l = idx / HIDP, j = idx - l * HIDP;
        b1p[idx] = (j < HID) ? b1[l * HID + j] : 0.f;
    }
    if (idx < NL * EMBP) {
        int l = idx / EMBP, j = idx - l * EMBP;
        b2p[idx] = (j < EMB) ? b2[l * EMB + j] : 0.f;
    }
    if (idx < NN) deg[idx] = 0;
}

// vectorized final BN: thread = one float4 chunk (75 per row)
__global__ void k_bnapply(const float* __restrict__ h2,
                          const float* __restrict__ gamma, const float* __restrict__ beta,
                          const float* __restrict__ stats,
                          float* __restrict__ dst) {
    int idx = blockIdx.x * blockDim.x + threadIdx.x;
    if (idx >= NN * 75) return;
    int r = idx / 75;
    int c = idx - r * 75;
    const float inv_n = 1.f / NN;
    float4 s = ((const float4*)stats)[c];
    float4 q = ((const float4*)(stats + EMB))[c];
    float4 g = ((const float4*)gamma)[c];
    float4 be = ((const float4*)beta)[c];
    float4 xv = ((const float4*)(h2 + (size_t)r * EMBP))[c];
    float4 y;
    float m, var;
    m = s.x * inv_n; var = q.x * inv_n - m * m; y.x = (xv.x - m) * rsqrtf(var + 1e-5f) * g.x + be.x;
    m = s.y * inv_n; var = q.y * inv_n - m * m; y.y = (xv.y - m) * rsqrtf(var + 1e-5f) * g.y + be.y;
    m = s.z * inv_n; var = q.z * inv_n - m * m; y.z = (xv.z - m) * rsqrtf(var + 1e-5f) * g.z + be.z;
    m = s.w * inv_n; var = q.w * inv_n - m * m; y.w = (xv.w - m) * rsqrtf(var + 1e-5f) * g.w + be.w;
    ((float4*)(dst + (size_t)r * EMB))[c] = y;
}

// ================= launch =================
extern "C" void kernel_launch(void* const* d_in, const int* in_sizes, int n_in,
                              void* d_out, int out_size) {
    const int*   x     = (const int*)d_in[0];
    const int*   ei    = (const int*)d_in[1];
    const int*   ea    = (const int*)d_in[2];
    const float* xe1   = (const float*)d_in[3];
    const float* xe2   = (const float*)d_in[4];
    const float* e1    = (const float*)d_in[5];
    const float* e2    = (const float*)d_in[6];
    const float* W1    = (const float*)d_in[7];
    const float* b1    = (const float*)d_in[8];
    const float* W2    = (const float*)d_in[9];
    const float* b2    = (const float*)d_in[10];
    const float* gamma = (const float*)d_in[11];
    const float* beta  = (const float*)d_in[12];
    float* out = (float*)d_out;

    float *h, *h2, *b1p, *b2p, *stats;
    __nv_bfloat16 *ah, *al, *t1h, *t1l, *w1th, *w1tl, *w2th, *w2tl;
    int *deg, *rowptr, *cursor, *bsum, *boff, *csr;
    cudaGetSymbolAddress((void**)&h, g_h);
    cudaGetSymbolAddress((void**)&h2, g_h2);
    cudaGetSymbolAddress((void**)&ah, g_ah);
    cudaGetSymbolAddress((void**)&al, g_al);
    cudaGetSymbolAddress((void**)&t1h, g_t1h);
    cudaGetSymbolAddress((void**)&t1l, g_t1l);
    cudaGetSymbolAddress((void**)&w1th, g_w1th);
    cudaGetSymbolAddress((void**)&w1tl, g_w1tl);
    cudaGetSymbolAddress((void**)&w2th, g_w2th);
    cudaGetSymbolAddress((void**)&w2tl, g_w2tl);
    cudaGetSymbolAddress((void**)&b1p, g_b1p);
    cudaGetSymbolAddress((void**)&b2p, g_b2p);
    cudaGetSymbolAddress((void**)&stats, g_stats);
    cudaGetSymbolAddress((void**)&deg, g_deg);
    cudaGetSymbolAddress((void**)&rowptr, g_rowptr);
    cudaGetSymbolAddress((void**)&cursor, g_cursor);
    cudaGetSymbolAddress((void**)&bsum, g_bsum);
    cudaGetSymbolAddress((void**)&boff, g_boff);
    cudaGetSymbolAddress((void**)&csr, g_csr);

    const int SMEMSZ = 4 * 24576;  // 96KB -> 2 CTAs/SM
    cudaFuncSetAttribute((const void*)k_gemm<EMBP, EMBP, HIDP, 1>,
                         cudaFuncAttributeMaxDynamicSharedMemorySize, SMEMSZ);
    cudaFuncSetAttribute((const void*)k_gemm<HIDP, HIDE, EMBP, 2>,
                         cudaFuncAttributeMaxDynamicSharedMemorySize, SMEMSZ);

    const int TP = 256;

    // one-time prep (tiled transposes; prepb also zeroes deg)
    {
        dim3 thr(32, 8);
        dim3 g1(HIDP / 32, EMBP / 32, NL);   // W1: K=EMB,N=HID -> [HIDP, EMBP]
        dim3 g2(EMBP / 32, HIDP / 32, NL);   // W2: K=HID,N=EMB -> [EMBP, HIDP]
        k_prepw<<<g1, thr>>>(W1, w1th, w1tl, EMB, HID, EMBP, HIDP);
        k_prepw<<<g2, thr>>>(W2, w2th, w2tl, HID, EMB, HIDP, EMBP);
    }
    k_prepb<<<(NN + TP - 1) / TP, TP>>>(b1, b2, b1p, b2p, deg);  // NN > NL*HIDP
    k_init<<<(NN * 75 + TP - 1) / TP, TP>>>(x, xe1, xe2, h);

    // CSR build
    k_csr_hist<<<(NE + TP - 1) / TP, TP>>>(ei, deg);
    k_scan1<<<NB_SCAN, 256>>>(deg, rowptr, bsum);
    k_scan2<<<1, 128>>>(bsum, boff);
    k_scan3<<<(NN + TP - 1) / TP, TP>>>(rowptr, boff, cursor);
    k_fill<<<(NE + TP - 1) / TP, TP>>>(ei, ea, cursor, csr);

    const int gGather = (NN * 32 + TP - 1) / TP;

    for (int l = 0; l < NL; l++) {
        if (l == 0) {
            k_gather<false><<<gGather, TP>>>(csr, rowptr,
                                             e1, e2, h,
                                             nullptr, nullptr, nullptr, ah, al);
        } else {
            k_gather<true><<<gGather, TP>>>(csr, rowptr,
                                            e1 + (size_t)l * 6 * EMB,
                                            e2 + (size_t)l * 3 * EMB, h2,
                                            stats,
                                            gamma + (size_t)(l - 1) * EMB,
                                            beta + (size_t)(l - 1) * EMB, ah, al);
        }

        k_gemm<EMBP, EMBP, HIDP, 1><<<dim3(HIDP / 64, MP / 128), 256, SMEMSZ>>>(
            ah, al,
            w1th + (size_t)l * HIDP * EMBP, w1tl + (size_t)l * HIDP * EMBP,
            b1p + l * HIDP, t1h, t1l, stats);

        k_gemm<HIDP, HIDE, EMBP, 2><<<dim3(EMBP / 64, MP / 128), 256, SMEMSZ>>>(
            t1h, t1l,
            w2th + (size_t)l * EMBP * HIDP, w2tl + (size_t)l * EMBP * HIDP,
            b2p + l * EMBP, h2, nullptr, stats);
    }

    // final BN (no relu) -> out (vectorized)
    k_bnapply<<<(NN * 75 + TP - 1) / TP, TP>>>(h2, gamma + (size_t)(NL - 1) * EMB,
                                               beta + (size_t)(NL - 1) * EMB, stats, out);
}

// round 15
// speedup vs baseline: 1.0512x; 1.0051x over previous
#include <cuda_runtime.h>
#include <cuda_bf16.h>
#include <cstdint>

#define NN    30000
#define MP    30080          // rows padded to 235*128
#define NE    240000
#define EMB   300
#define EMBP  320            // padded emb
#define HID   600
#define HIDP  640            // padded hidden (stride)
#define HIDE  608            // effective K for GEMM2 (cols 608..639 of t1 are exact zeros)
#define NL    5
#define NB_SCAN 118          // ceil(30000/256)

// ---------------- scratch (device globals: allocation-free, zero-init) ----------------
__device__ float          g_h  [(size_t)NN * EMBP];     // layer-0 features only
__device__ float          g_h2 [(size_t)MP * EMBP];     // raw GEMM2 output (pre-BN)
__device__ __nv_bfloat16  g_ah [(size_t)MP * EMBP];     // pad rows/cols stay 0
__device__ __nv_bfloat16  g_al [(size_t)MP * EMBP];
__device__ __nv_bfloat16  g_t1h[(size_t)MP * HIDP];
__device__ __nv_bfloat16  g_t1l[(size_t)MP * HIDP];
__device__ __nv_bfloat16  g_w1th[(size_t)NL * HIDP * EMBP]; // W1^T split [l][n=640][k=320]
__device__ __nv_bfloat16  g_w1tl[(size_t)NL * HIDP * EMBP];
__device__ __nv_bfloat16  g_w2th[(size_t)NL * EMBP * HIDP]; // W2^T split [l][n=320][k=640]
__device__ __nv_bfloat16  g_w2tl[(size_t)NL * EMBP * HIDP];
__device__ float          g_b1p[NL * HIDP];
__device__ float          g_b2p[NL * EMBP];
__device__ float          g_stats[2 * EMB];
// CSR scratch
__device__ int            g_deg[NN];
__device__ int            g_rowptr[NN + 1];
__device__ int            g_cursor[NN];
__device__ int            g_bsum[NB_SCAN];
__device__ int            g_boff[NB_SCAN];
__device__ int            g_csr[NE];     // packed: src | a0<<16 | a1<<20

// ================= PTX helpers =================
__device__ __forceinline__ uint32_t smem_u32(const void* p) {
    uint32_t a;
    asm("{ .reg .u64 t; cvta.to.shared.u64 t, %1; cvt.u32.u64 %0, t; }" : "=r"(a) : "l"(p));
    return a;
}
__device__ __forceinline__ void cpa16(uint32_t s, const void* g) {
    asm volatile("cp.async.cg.shared.global [%0], [%1], 16;" :: "r"(s), "l"(g) : "memory");
}
#define CP_COMMIT() asm volatile("cp.async.commit_group;" ::: "memory")
#define CP_WAIT(n)  asm volatile("cp.async.wait_group %0;" :: "n"(n) : "memory")

__device__ __forceinline__ void ldm4(uint32_t* r, uint32_t a) {
    asm volatile("ldmatrix.sync.aligned.m8n8.x4.shared.b16 {%0,%1,%2,%3}, [%4];"
                 : "=r"(r[0]), "=r"(r[1]), "=r"(r[2]), "=r"(r[3]) : "r"(a));
}
__device__ __forceinline__ void mma_bf16(float* c, const uint32_t* a, uint32_t b0, uint32_t b1) {
    asm volatile(
        "mma.sync.aligned.m16n8k16.row.col.f32.bf16.bf16.f32 "
        "{%0,%1,%2,%3}, {%4,%5,%6,%7}, {%8,%9}, {%0,%1,%2,%3};"
        : "+f"(c[0]), "+f"(c[1]), "+f"(c[2]), "+f"(c[3])
        : "r"(a[0]), "r"(a[1]), "r"(a[2]), "r"(a[3]), "r"(b0), "r"(b1));
}

// SW64 swizzle for 64-byte rows
__device__ __forceinline__ uint32_t sw64(uint32_t off) {
    return off ^ ((off >> 3) & 0x30);
}

// ================= HMMA GEMM (bf16x3 split) — R7/R11 config, frozen =================
// CTA tile 128x64, 8 warps (4M x 2N), warp tile 32x32.
// K-chunk 32, 4-stage cp.async pipeline (24KB/stage, 96KB total -> 2 CTAs/SM).
// KP = row stride (elements); KEFF = contracted K (KEFF <= KP, multiple of 32).
// EPI==1: relu(acc+bias) -> split bf16 to O1/O2 (row stride NP); block(0,0) zeroes stats
// EPI==2: acc+bias -> f32 O1 (row stride NP), fused BN column sum/sumsq into stats
template <int KP, int KEFF, int NP, int EPI>
__global__ void __launch_bounds__(256, 2)
k_gemm(const __nv_bfloat16* __restrict__ Ah, const __nv_bfloat16* __restrict__ Al,
       const __nv_bfloat16* __restrict__ Bh, const __nv_bfloat16* __restrict__ Bl,
       const float* __restrict__ bias, void* __restrict__ O1, void* __restrict__ O2,
       float* __restrict__ stats)
{
    constexpr int NKC = KEFF / 32;
    constexpr uint32_t STG = 24576;
    constexpr uint32_t A_H = 0, A_L = 8192, B_H = 16384, B_L = 20480;

    __shared__ float sstat[128];        // [0:64) col sums, [64:128) col sumsqs

    extern __shared__ char smem[];
    const uint32_t sb = smem_u32(smem);
    const int tid  = threadIdx.x;
    const int lane = tid & 31;
    const int warp = tid >> 5;
    const int wm   = warp & 3;           // 0..3 (M)
    const int wn   = warp >> 2;          // 0..1 (N)
    const int bm   = blockIdx.y * 128;
    const int bn   = blockIdx.x * 64;

    if (EPI == 1 && blockIdx.x == 0 && blockIdx.y == 0) {
        for (int i = tid; i < 2 * EMB; i += 256) stats[i] = 0.f;
    }
    if (EPI == 2 && tid < 128) sstat[tid] = 0.f;

    const size_t rs = (size_t)KP * 2;    // row stride bytes

    auto load_stage = [&](int buf, int kc) {
        uint32_t s0 = sb + buf * STG;
        int k0 = kc * 32;
        const char* ahp = (const char*)(Ah + (size_t)bm * KP + k0);
        const char* alp = (const char*)(Al + (size_t)bm * KP + k0);
        const char* bhp = (const char*)(Bh + (size_t)bn * KP + k0);
        const char* blp = (const char*)(Bl + (size_t)bn * KP + k0);
        #pragma unroll
        for (int i = 0; i < 2; i++) {       // A: 128 rows x 4 x 16B = 512 chunks/half
            int idx = tid + 256 * i;
            int r = idx >> 2, c = (idx & 3) * 16;
            uint32_t sw = sw64((uint32_t)(r * 64 + c));
            cpa16(s0 + A_H + sw, ahp + (size_t)r * rs + c);
            cpa16(s0 + A_L + sw, alp + (size_t)r * rs + c);
        }
        {                                   // B: 64 rows x 4 x 16B = 256 chunks/half
            int r = tid >> 2, c = (tid & 3) * 16;
            uint32_t sw = sw64((uint32_t)(r * 64 + c));
            cpa16(s0 + B_H + sw, bhp + (size_t)r * rs + c);
            cpa16(s0 + B_L + sw, blp + (size_t)r * rs + c);
        }
    };

    float acc[2][4][4];
    #pragma unroll
    for (int mi = 0; mi < 2; mi++)
        #pragma unroll
        for (int ni = 0; ni < 4; ni++)
            #pragma unroll
            for (int q = 0; q < 4; q++) acc[mi][ni][q] = 0.f;

    load_stage(0, 0); CP_COMMIT();
    load_stage(1, 1); CP_COMMIT();
    load_stage(2, 2); CP_COMMIT();

    for (int k = 0; k < NKC; k++) {
        CP_WAIT(2);
        __syncthreads();                    // stage k visible; buf (k+3)&3 free
        if (k + 3 < NKC) load_stage((k + 3) & 3, k + 3);
        CP_COMMIT();

        uint32_t s0 = sb + (k & 3) * STG;
        #pragma unroll
        for (int ks = 0; ks < 2; ks++) {
            uint32_t ahf[2][4], alf[2][4], bhf[2][4], blf[2][4];
            #pragma unroll
            for (int mi = 0; mi < 2; mi++) {
                uint32_t off = (uint32_t)((wm * 32 + mi * 16 + (lane & 15)) * 64
                                          + ks * 32 + ((lane >> 4) << 4));
                off = sw64(off);
                ldm4(ahf[mi], s0 + A_H + off);
                ldm4(alf[mi], s0 + A_L + off);
            }
            #pragma unroll
            for (int nj = 0; nj < 2; nj++) {
                int rr = wn * 32 + nj * 16 + (lane & 7) + ((lane >> 4) << 3);
                uint32_t off = (uint32_t)(rr * 64 + ks * 32 + (((lane >> 3) & 1) << 4));
                off = sw64(off);
                ldm4(bhf[nj], s0 + B_H + off);
                ldm4(blf[nj], s0 + B_L + off);
            }
            #pragma unroll
            for (int mi = 0; mi < 2; mi++)
                #pragma unroll
                for (int ni = 0; ni < 4; ni++) {
                    const uint32_t* bh2 = &bhf[ni >> 1][(ni & 1) * 2];
                    const uint32_t* bl2 = &blf[ni >> 1][(ni & 1) * 2];
                    mma_bf16(acc[mi][ni], ahf[mi], bh2[0], bh2[1]);
                    mma_bf16(acc[mi][ni], ahf[mi], bl2[0], bl2[1]);
                    mma_bf16(acc[mi][ni], alf[mi], bh2[0], bh2[1]);
                }
        }
    }

    // epilogue
    #pragma unroll
    for (int mi = 0; mi < 2; mi++) {
        int r0 = bm + wm * 32 + mi * 16 + (lane >> 2);
        #pragma unroll
        for (int ni = 0; ni < 4; ni++) {
            int col = bn + wn * 32 + ni * 8 + ((lane & 3) << 1);
            float bb0 = bias[col], bb1 = bias[col + 1];
            float v00 = acc[mi][ni][0] + bb0, v01 = acc[mi][ni][1] + bb1;
            float v10 = acc[mi][ni][2] + bb0, v11 = acc[mi][ni][3] + bb1;
            if (EPI == 1) {
                v00 = fmaxf(v00, 0.f); v01 = fmaxf(v01, 0.f);
                v10 = fmaxf(v10, 0.f); v11 = fmaxf(v11, 0.f);
                __nv_bfloat162* oh = (__nv_bfloat162*)O1;
                __nv_bfloat162* ol = (__nv_bfloat162*)O2;
                __nv_bfloat16 h00 = __float2bfloat16(v00), h01 = __float2bfloat16(v01);
                __nv_bfloat16 h10 = __float2bfloat16(v10), h11 = __float2bfloat16(v11);
                __nv_bfloat162 t0; t0.x = h00; t0.y = h01;
                __nv_bfloat162 t1; t1.x = h10; t1.y = h11;
                __nv_bfloat162 u0; u0.x = __float2bfloat16(v00 - __bfloat162float(h00));
                                   u0.y = __float2bfloat16(v01 - __bfloat162float(h01));
                __nv_bfloat162 u1; u1.x = __float2bfloat16(v10 - __bfloat162float(h10));
                                   u1.y = __float2bfloat16(v11 - __bfloat162float(h11));
                oh[((size_t)r0 * NP + col) >> 1] = t0;
                oh[((size_t)(r0 + 8) * NP + col) >> 1] = t1;
                ol[((size_t)r0 * NP + col) >> 1] = u0;
                ol[((size_t)(r0 + 8) * NP + col) >> 1] = u1;
            } else {
                float2* o = (float2*)O1;
                float2 f0; f0.x = v00; f0.y = v01;
                float2 f1; f1.x = v10; f1.y = v11;
                o[((size_t)r0 * NP + col) >> 1] = f0;
                o[((size_t)(r0 + 8) * NP + col) >> 1] = f1;
                float m0 = (r0 < NN) ? 1.f : 0.f;
                float m1 = (r0 + 8 < NN) ? 1.f : 0.f;
                float s0 = m0 * v00 + m1 * v10;
                float s1 = m0 * v01 + m1 * v11;
                float q0 = m0 * v00 * v00 + m1 * v10 * v10;
                float q1 = m0 * v01 * v01 + m1 * v11 * v11;
                #pragma unroll
                for (int d = 4; d < 32; d <<= 1) {
                    s0 += __shfl_xor_sync(0xffffffff, s0, d);
                    s1 += __shfl_xor_sync(0xffffffff, s1, d);
                    q0 += __shfl_xor_sync(0xffffffff, q0, d);
                    q1 += __shfl_xor_sync(0xffffffff, q1, d);
                }
                if (lane < 4) {
                    int cl = wn * 32 + ni * 8 + ((lane & 3) << 1);
                    atomicAdd(&sstat[cl], s0);
                    atomicAdd(&sstat[cl + 1], s1);
                    atomicAdd(&sstat[64 + cl], q0);
                    atomicAdd(&sstat[64 + cl + 1], q1);
                }
            }
        }
    }
    if (EPI == 2) {
        __syncthreads();
        if (tid < 64) {
            int c = bn + tid;
            if (c < EMB) {
                atomicAdd(&stats[c], sstat[tid]);
                atomicAdd(&stats[EMB + c], sstat[64 + tid]);
            }
        }
    }
}

// ================= CSR build =================
__global__ void k_csr_zero(int* __restrict__ deg) {
    int i = blockIdx.x * blockDim.x + threadIdx.x;
    if (i < NN) deg[i] = 0;
}
__global__ void k_csr_hist(const int* __restrict__ ei, int* __restrict__ deg) {
    int e = blockIdx.x * blockDim.x + threadIdx.x;
    if (e < NE) atomicAdd(&deg[ei[NE + e]], 1);
}
__global__ void k_scan1(const int* __restrict__ deg, int* __restrict__ rowptr,
                        int* __restrict__ bsum) {
    __shared__ int sh[256];
    int t = threadIdx.x;
    int i = blockIdx.x * 256 + t;
    int v = (i < NN) ? deg[i] : 0;
    sh[t] = v;
    __syncthreads();
    #pragma unroll
    for (int off = 1; off < 256; off <<= 1) {
        int x = (t >= off) ? sh[t - off] : 0;
        __syncthreads();
        if (t >= off) sh[t] += x;
        __syncthreads();
    }
    if (i < NN) rowptr[i] = sh[t] - v;
    if (t == 255) bsum[blockIdx.x] = sh[255];
}
__global__ void k_scan2(const int* __restrict__ bsum, int* __restrict__ boff) {
    __shared__ int sh[128];
    int t = threadIdx.x;
    int v = (t < NB_SCAN) ? bsum[t] : 0;
    sh[t] = v;
    __syncthreads();
    #pragma unroll
    for (int off = 1; off < 128; off <<= 1) {
        int x = (t >= off) ? sh[t - off] : 0;
        __syncthreads();
        if (t >= off) sh[t] += x;
        __syncthreads();
    }
    if (t < NB_SCAN) boff[t] = sh[t] - v;
}
__global__ void k_scan3(int* __restrict__ rowptr, const int* __restrict__ boff,
                        int* __restrict__ cursor) {
    int i = blockIdx.x * blockDim.x + threadIdx.x;
    if (i < NN) {
        int r = rowptr[i] + boff[i >> 8];
        rowptr[i] = r;
        cursor[i] = r;
    }
    if (i == 0) rowptr[NN] = NE;
}
__global__ void k_fill(const int* __restrict__ ei, const int* __restrict__ ea,
                       int* __restrict__ cursor, int* __restrict__ csr) {
    int e = blockIdx.x * blockDim.x + threadIdx.x;
    if (e < NE) {
        int d = ei[NE + e];
        int p = atomicAdd(&cursor[d], 1);
        csr[p] = ei[e] | (ea[2 * e] << 16) | (ea[2 * e + 1] << 20);
    }
}

// ================= gather aggregate (warp per node) — R12 version, frozen ============
template <bool BN>
__global__ void __launch_bounds__(256)
k_gather(const int* __restrict__ csr, const int* __restrict__ rowptr,
         const float* __restrict__ e1l, const float* __restrict__ e2l,
         const float* __restrict__ hbuf,
         const float* __restrict__ stats, const float* __restrict__ gamma,
         const float* __restrict__ beta,
         __nv_bfloat16* __restrict__ ah, __nv_bfloat16* __restrict__ al)
{
    int v = (blockIdx.x * blockDim.x + threadIdx.x) >> 5;
    int lane = threadIdx.x & 31;
    if (v >= NN) return;

    const int c0 = lane, c1 = lane + 32, c2 = lane + 64;   // float4 chunks
    const bool has2 = (c2 < 75);

    float4 A0, B0, A1, B1, A2, B2;
    if (BN) {
        const float inv_n = 1.f / NN;
        const float4* sS = (const float4*)stats;
        const float4* sQ = (const float4*)(stats + EMB);
        const float4* sG = (const float4*)gamma;
        const float4* sB = (const float4*)beta;
        auto coef = [&](int c, float4& A, float4& B) {
            float4 s = sS[c], q = sQ[c], g = sG[c], be = sB[c];
            float m, var;
            m = s.x * inv_n; var = q.x * inv_n - m * m; A.x = g.x * rsqrtf(var + 1e-5f); B.x = be.x - m * A.x;
            m = s.y * inv_n; var = q.y * inv_n - m * m; A.y = g.y * rsqrtf(var + 1e-5f); B.y = be.y - m * A.y;
            m = s.z * inv_n; var = q.z * inv_n - m * m; A.z = g.z * rsqrtf(var + 1e-5f); B.z = be.z - m * A.z;
            m = s.w * inv_n; var = q.w * inv_n - m * m; A.w = g.w * rsqrtf(var + 1e-5f); B.w = be.w - m * A.w;
        };
        coef(c0, A0, B0);
        coef(c1, A1, B1);
        if (has2) coef(c2, A2, B2);
    }

    auto bnr = [&](float4 x, const float4& A, const float4& B) {
        if (!BN) return x;
        float4 y;
        y.x = fmaxf(fmaf(A.x, x.x, B.x), 0.f);
        y.y = fmaxf(fmaf(A.y, x.y, B.y), 0.f);
        y.z = fmaxf(fmaf(A.z, x.z, B.z), 0.f);
        y.w = fmaxf(fmaf(A.w, x.w, B.w), 0.f);
        return y;
    };

    float4 f0, f1, f2;
    {
        const float4* hv = (const float4*)(hbuf + (size_t)v * EMBP);
        f0 = bnr(hv[c0], A0, B0);
        f1 = bnr(hv[c1], A1, B1);
        f2 = has2 ? bnr(hv[c2], A2, B2) : make_float4(0.f, 0.f, 0.f, 0.f);
    }
    int n10 = 0, n11 = 0, n12 = 0, n13 = 0, n14 = 1, n15 = 0;
    int n20 = 1, n21 = 0, n22 = 0;

    int s = rowptr[v], e = rowptr[v + 1];
    for (int p = s; p < e; p++) {
        int w = csr[p];
        int src = w & 0xFFFF;
        int a0 = (w >> 16) & 15, a1 = w >> 20;
        n10 += (a0 == 0); n11 += (a0 == 1); n12 += (a0 == 2);
        n13 += (a0 == 3); n14 += (a0 == 4); n15 += (a0 == 5);
        n20 += (a1 == 0); n21 += (a1 == 1); n22 += (a1 == 2);
        const float4* hs = (const float4*)(hbuf + (size_t)src * EMBP);
        float4 x0 = bnr(hs[c0], A0, B0);
        float4 x1 = bnr(hs[c1], A1, B1);
        f0.x += x0.x; f0.y += x0.y; f0.z += x0.z; f0.w += x0.w;
        f1.x += x1.x; f1.y += x1.y; f1.z += x1.z; f1.w += x1.w;
        if (has2) {
            float4 x2 = bnr(hs[c2], A2, B2);
            f2.x += x2.x; f2.y += x2.y; f2.z += x2.z; f2.w += x2.w;
        }
    }
    auto addw = [&](const float* row, float wgt) {
        const float4* t = (const float4*)row;
        float4 x0 = t[c0], x1 = t[c1];
        f0.x += wgt * x0.x; f0.y += wgt * x0.y; f0.z += wgt * x0.z; f0.w += wgt * x0.w;
        f1.x += wgt * x1.x; f1.y += wgt * x1.y; f1.z += wgt * x1.z; f1.w += wgt * x1.w;
        if (has2) {
            float4 x2 = t[c2];
            f2.x += wgt * x2.x; f2.y += wgt * x2.y; f2.z += wgt * x2.z; f2.w += wgt * x2.w;
        }
    };
    if (n10) addw(e1l + 0 * EMB, (float)n10);
    if (n11) addw(e1l + 1 * EMB, (float)n11);
    if (n12) addw(e1l + 2 * EMB, (float)n12);
    if (n13) addw(e1l + 3 * EMB, (float)n13);
    if (n14) addw(e1l + 4 * EMB, (float)n14);
    if (n15) addw(e1l + 5 * EMB, (float)n15);
    if (n20) addw(e2l + 0 * EMB, (float)n20);
    if (n21) addw(e2l + 1 * EMB, (float)n21);
    if (n22) addw(e2l + 2 * EMB, (float)n22);

    auto wr = [&](int c, float4 f) {
        __nv_bfloat16 h0 = __float2bfloat16(f.x), h1 = __float2bfloat16(f.y);
        __nv_bfloat16 h2b = __float2bfloat16(f.z), h3 = __float2bfloat16(f.w);
        __nv_bfloat162 p0; p0.x = h0;  p0.y = h1;
        __nv_bfloat162 p1; p1.x = h2b; p1.y = h3;
        __nv_bfloat162 q0; q0.x = __float2bfloat16(f.x - __bfloat162float(h0));
                           q0.y = __float2bfloat16(f.y - __bfloat162float(h1));
        __nv_bfloat162 q1; q1.x = __float2bfloat16(f.z - __bfloat162float(h2b));
                           q1.y = __float2bfloat16(f.w - __bfloat162float(h3));
        size_t base = ((size_t)v * EMBP + 4 * c) >> 1;
        ((__nv_bfloat162*)ah)[base] = p0;
        ((__nv_bfloat162*)ah)[base + 1] = p1;
        ((__nv_bfloat162*)al)[base] = q0;
        ((__nv_bfloat162*)al)[base + 1] = q1;
    };
    wr(c0, f0);
    wr(c1, f1);
    if (has2) wr(c2, f2);
}

// ================= misc kernels =================
// vectorized init: thread = one float4 chunk (75 per row)
__global__ void k_init(const int* __restrict__ x,
                       const float* __restrict__ xe1,
                       const float* __restrict__ xe2,
                       float* __restrict__ h) {
    int idx = blockIdx.x * blockDim.x + threadIdx.x;
    if (idx >= NN * 75) return;
    int i = idx / 75;
    int c = idx - i * 75;
    int x0 = x[2 * i], x1 = x[2 * i + 1];
    float4 u = ((const float4*)(xe1 + (size_t)x0 * EMB))[c];
    float4 w = ((const float4*)(xe2 + (size_t)x1 * EMB))[c];
    float4 r;
    r.x = u.x + w.x; r.y = u.y + w.y; r.z = u.z + w.z; r.w = u.w + w.w;
    ((float4*)(h + (size_t)i * EMBP))[c] = r;
}

// Tiled transpose + split for BOTH weights in one launch.
// blockIdx.z in [0, 2*NL): z < NL -> W1 layer z; z >= NL -> W2 layer z-NL.
// W1: K=EMB, N=HID, grid (HIDP/32, EMBP/32); W2: K=HID, N=EMB, grid (EMBP/32, HIDP/32).
// Grid is (max dims); out-of-range tiles guarded.
__global__ void k_prepw(const float* __restrict__ W1, const float* __restrict__ W2,
                        __nv_bfloat16* __restrict__ w1h, __nv_bfloat16* __restrict__ w1l,
                        __nv_bfloat16* __restrict__ w2h, __nv_bfloat16* __restrict__ w2l) {
    __shared__ float sm[32][33];
    const bool isW2 = (blockIdx.z >= NL);
    const int l = isW2 ? (blockIdx.z - NL) : blockIdx.z;
    const int K  = isW2 ? HID  : EMB;
    const int N  = isW2 ? EMB  : HID;
    const int KP = isW2 ? HIDP : EMBP;
    const int NP = isW2 ? EMBP : HIDP;
    const int gx = NP / 32, gy = KP / 32;
    if ((int)blockIdx.x >= gx || (int)blockIdx.y >= gy) return;
    const float* Wl = (isW2 ? W2 : W1) + (size_t)l * K * N;
    __nv_bfloat16* whl = (isW2 ? w2h : w1h) + (size_t)l * NP * KP;
    __nv_bfloat16* wll = (isW2 ? w2l : w1l) + (size_t)l * NP * KP;
    int n0 = blockIdx.x * 32, k0 = blockIdx.y * 32;
    int tx = threadIdx.x, ty = threadIdx.y;    // 32 x 8
    #pragma unroll
    for (int s = 0; s < 4; s++) {
        int k = k0 + ty + 8 * s;
        int n = n0 + tx;
        sm[ty + 8 * s][tx] = (k < K && n < N) ? Wl[(size_t)k * N + n] : 0.f;
    }
    __syncthreads();
    #pragma unroll
    for (int s = 0; s < 4; s++) {
        int n = n0 + ty + 8 * s;
        int k = k0 + tx;
        float v = sm[tx][ty + 8 * s];
        __nv_bfloat16 h = __float2bfloat16(v);
        whl[(size_t)n * KP + k] = h;
        wll[(size_t)n * KP + k] = __float2bfloat16(v - __bfloat162float(h));
    }
}

__global__ void k_prepb(const float* __restrict__ b1, const float* __restrict__ b2,
                        float* __restrict__ b1p, float* __restrict__ b2p) {
    int idx = blockIdx.x * blockDim.x + threadIdx.x;
    if (idx < NL * HIDP) {
        int l = idx / HIDP, j = idx - l * HIDP;
        b1p[idx] = (j < HID) ? b1[l * HID + j] : 0.f;
    }
    if (idx < NL * EMBP) {
        int l = idx / EMBP, j = idx - l * EMBP;
        b2p[idx] = (j < EMB) ? b2[l * EMB + j] : 0.f;
    }
}

// vectorized final BN: thread = one float4 chunk (75 per row)
__global__ void k_bnapply(const float* __restrict__ h2,
                          const float* __restrict__ gamma, const float* __restrict__ beta,
                          const float* __restrict__ stats,
                          float* __restrict__ dst) {
    int idx = blockIdx.x * blockDim.x + threadIdx.x;
    if (idx >= NN * 75) return;
    int r = idx / 75;
    int c = idx - r * 75;
    const float inv_n = 1.f / NN;
    float4 s = ((const float4*)stats)[c];
    float4 q = ((const float4*)(stats + EMB))[c];
    float4 g = ((const float4*)gamma)[c];
    float4 be = ((const float4*)beta)[c];
    float4 xv = ((const float4*)(h2 + (size_t)r * EMBP))[c];
    float4 y;
    float m, var;
    m = s.x * inv_n; var = q.x * inv_n - m * m; y.x = (xv.x - m) * rsqrtf(var + 1e-5f) * g.x + be.x;
    m = s.y * inv_n; var = q.y * inv_n - m * m; y.y = (xv.y - m) * rsqrtf(var + 1e-5f) * g.y + be.y;
    m = s.z * inv_n; var = q.z * inv_n - m * m; y.z = (xv.z - m) * rsqrtf(var + 1e-5f) * g.z + be.z;
    m = s.w * inv_n; var = q.w * inv_n - m * m; y.w = (xv.w - m) * rsqrtf(var + 1e-5f) * g.w + be.w;
    ((float4*)(dst + (size_t)r * EMB))[c] = y;
}

// ================= launch =================
extern "C" void kernel_launch(void* const* d_in, const int* in_sizes, int n_in,
                              void* d_out, int out_size) {
    const int*   x     = (const int*)d_in[0];
    const int*   ei    = (const int*)d_in[1];
    const int*   ea    = (const int*)d_in[2];
    const float* xe1   = (const float*)d_in[3];
    const float* xe2   = (const float*)d_in[4];
    const float* e1    = (const float*)d_in[5];
    const float* e2    = (const float*)d_in[6];
    const float* W1    = (const float*)d_in[7];
    const float* b1    = (const float*)d_in[8];
    const float* W2    = (const float*)d_in[9];
    const float* b2    = (const float*)d_in[10];
    const float* gamma = (const float*)d_in[11];
    const float* beta  = (const float*)d_in[12];
    float* out = (float*)d_out;

    float *h, *h2, *b1p, *b2p, *stats;
    __nv_bfloat16 *ah, *al, *t1h, *t1l, *w1th, *w1tl, *w2th, *w2tl;
    int *deg, *rowptr, *cursor, *bsum, *boff, *csr;
    cudaGetSymbolAddress((void**)&h, g_h);
    cudaGetSymbolAddress((void**)&h2, g_h2);
    cudaGetSymbolAddress((void**)&ah, g_ah);
    cudaGetSymbolAddress((void**)&al, g_al);
    cudaGetSymbolAddress((void**)&t1h, g_t1h);
    cudaGetSymbolAddress((void**)&t1l, g_t1l);
    cudaGetSymbolAddress((void**)&w1th, g_w1th);
    cudaGetSymbolAddress((void**)&w1tl, g_w1tl);
    cudaGetSymbolAddress((void**)&w2th, g_w2th);
    cudaGetSymbolAddress((void**)&w2tl, g_w2tl);
    cudaGetSymbolAddress((void**)&b1p, g_b1p);
    cudaGetSymbolAddress((void**)&b2p, g_b2p);
    cudaGetSymbolAddress((void**)&stats, g_stats);
    cudaGetSymbolAddress((void**)&deg, g_deg);
    cudaGetSymbolAddress((void**)&rowptr, g_rowptr);
    cudaGetSymbolAddress((void**)&cursor, g_cursor);
    cudaGetSymbolAddress((void**)&bsum, g_bsum);
    cudaGetSymbolAddress((void**)&boff, g_boff);
    cudaGetSymbolAddress((void**)&csr, g_csr);

    const int SMEMSZ = 4 * 24576;  // 96KB -> 2 CTAs/SM
    cudaFuncSetAttribute((const void*)k_gemm<EMBP, EMBP, HIDP, 1>,
                         cudaFuncAttributeMaxDynamicSharedMemorySize, SMEMSZ);
    cudaFuncSetAttribute((const void*)k_gemm<HIDP, HIDE, EMBP, 2>,
                         cudaFuncAttributeMaxDynamicSharedMemorySize, SMEMSZ);

    const int TP = 256;

    // one-time prep: fused W1+W2 transpose/split (grid covers max dims, guarded)
    {
        dim3 thr(32, 8);
        dim3 g(HIDP / 32, HIDP / 32, 2 * NL);   // max(gx)=20, max(gy)=20
        k_prepw<<<g, thr>>>(W1, W2, w1th, w1tl, w2th, w2tl);
    }
    k_prepb<<<(NL * HIDP + TP - 1) / TP, TP>>>(b1, b2, b1p, b2p);
    k_init<<<(NN * 75 + TP - 1) / TP, TP>>>(x, xe1, xe2, h);

    // CSR build
    k_csr_zero<<<(NN + TP - 1) / TP, TP>>>(deg);
    k_csr_hist<<<(NE + TP - 1) / TP, TP>>>(ei, deg);
    k_scan1<<<NB_SCAN, 256>>>(deg, rowptr, bsum);
    k_scan2<<<1, 128>>>(bsum, boff);
    k_scan3<<<(NN + TP - 1) / TP, TP>>>(rowptr, boff, cursor);
    k_fill<<<(NE + TP - 1) / TP, TP>>>(ei, ea, cursor, csr);

    const int gGather = (NN * 32 + TP - 1) / TP;

    for (int l = 0; l < NL; l++) {
        if (l == 0) {
            k_gather<false><<<gGather, TP>>>(csr, rowptr,
                                             e1, e2, h,
                                             nullptr, nullptr, nullptr, ah, al);
        } else {
            k_gather<true><<<gGather, TP>>>(csr, rowptr,
                                            e1 + (size_t)l * 6 * EMB,
                                            e2 + (size_t)l * 3 * EMB, h2,
                                            stats,
                                            gamma + (size_t)(l - 1) * EMB,
                                            beta + (size_t)(l - 1) * EMB, ah, al);
        }

        k_gemm<EMBP, EMBP, HIDP, 1><<<dim3(HIDP / 64, MP / 128), 256, SMEMSZ>>>(
            ah, al,
            w1th + (size_t)l * HIDP * EMBP, w1tl + (size_t)l * HIDP * EMBP,
            b1p + l * HIDP, t1h, t1l, stats);

        k_gemm<HIDP, HIDE, EMBP, 2><<<dim3(EMBP / 64, MP / 128), 256, SMEMSZ>>>(
            t1h, t1l,
            w2th + (size_t)l * EMBP * HIDP, w2tl + (size_t)l * EMBP * HIDP,
            b2p + l * EMBP, h2, nullptr, stats);
    }

    // final BN (no relu) -> out (vectorized)
    k_bnapply<<<(NN * 75 + TP - 1) / TP, TP>>>(h2, gamma + (size_t)(NL - 1) * EMB,
                                               beta + (size_t)(NL - 1) * EMB, stats, out);
}